// round 5
// baseline (speedup 1.0000x reference)
#include <cuda_runtime.h>
#include <cuda_bf16.h>

// GCN 2-layer, CSR-gather formulation:
//   deg[v] = in-edge count ; dinv = rsqrt(deg+1)
//   h = X @ W                          (unscaled, f32x2-packed GEMM)
//   out[v] = relu(dinv[v]*(sum_{s->v} h[s]*dinv[s] + h[v]*dinv[v]) + b)
// CSR built once, reused by both layers. edge_index is int32.
// gemm layer-1 runs on a side stream concurrent with the CSR build.

#define MAXN 100000
#define HID 64
#define NEDGE_MAX 1600000
#define SCAN_B 512

__device__ float g_hs [MAXN * HID];
__device__ float g_h1 [MAXN * HID];
__device__ float g_dinv[MAXN];
__device__ int   g_deg [MAXN];
__device__ int   g_rowstart[MAXN + 1];
__device__ int   g_cursor[MAXN];
__device__ int   g_csrc[NEDGE_MAX];
__device__ int   g_bsum[256];

// packed fp32x2 fma: acc += a * b
__device__ __forceinline__ void fma2(float2& acc, const float2& a, const float2& b) {
    unsigned long long* pa = (unsigned long long*)&acc;
    asm("fma.rn.f32x2 %0, %1, %2, %0;"
        : "+l"(*pa)
        : "l"(*(const unsigned long long*)&a), "l"(*(const unsigned long long*)&b));
}

// ---------------------------------------------------------------------------
__global__ void deg_count_kernel(const int* __restrict__ dst, int E) {
    int i = blockIdx.x * blockDim.x + threadIdx.x;
    if (i < E) atomicAdd(&g_deg[dst[i]], 1);
}

// ---- scan part 1: per-block exclusive scan + block sums ----------------------
__global__ void scan1_kernel(int n) {
    __shared__ int sm[SCAN_B];
    int tid = threadIdx.x;
    int i = blockIdx.x * SCAN_B + tid;
    int v = (i < n) ? g_deg[i] : 0;
    sm[tid] = v;
    __syncthreads();
#pragma unroll
    for (int off = 1; off < SCAN_B; off <<= 1) {
        int t = (tid >= off) ? sm[tid - off] : 0;
        __syncthreads();
        sm[tid] += t;
        __syncthreads();
    }
    if (i < n) g_rowstart[i] = sm[tid] - v;
    if (tid == SCAN_B - 1) g_bsum[blockIdx.x] = sm[tid];
}

// ---- scan part 2 (fused): block re-scans bsum in smem; finalize rowstart,
//      cursor, dinv -----------------------------------------------------------
__global__ void scan23_kernel(int n, int E, int nb) {
    __shared__ int sb[256];
    int tid = threadIdx.x;
    int v = (tid < nb) ? g_bsum[tid] : 0;
    sb[tid] = v;
    __syncthreads();
#pragma unroll
    for (int off = 1; off < 256; off <<= 1) {
        int t = (tid >= off) ? sb[tid - off] : 0;
        __syncthreads();
        sb[tid] += t;
        __syncthreads();
    }
    // convert to exclusive in-place
    int excl = sb[tid] - v;
    __syncthreads();
    sb[tid] = excl;
    __syncthreads();

    int i = blockIdx.x * blockDim.x + tid;
    if (i < n) {
        int r = g_rowstart[i] + sb[i >> 9];
        g_rowstart[i] = r;
        g_cursor[i] = r;
        g_dinv[i] = rsqrtf((float)(g_deg[i] + 1));
    }
    if (i == 0) g_rowstart[n] = E;
}

__global__ void fill_kernel(const int* __restrict__ src,
                            const int* __restrict__ dst, int E) {
    int i = blockIdx.x * blockDim.x + threadIdx.x;
    if (i < E) {
        int pos = atomicAdd(&g_cursor[dst[i]], 1);
        g_csrc[pos] = src[i];
    }
}

// ---------------------------------------------------------------------------
// h[row] = X[row] @ W   (no scaling — dinv applied in gather)
// Block = 256 thr = 8 warps; each warp computes 8 rows x 64 cols.
// f32x2 packing over k: acc halves hold even-k / odd-k partial sums.
__global__ void gemm_kernel(const float* __restrict__ X,
                            const float* __restrict__ W,
                            float* __restrict__ out, int n) {
    __shared__ float2 Wp[32 * HID];      // 16 KB
    __shared__ float4 xs[64][16];        // 16 KB
    int tid = threadIdx.x;

#pragma unroll
    for (int i = tid; i < 32 * HID; i += 256) {
        int k2 = i >> 6, col = i & 63;
        Wp[i] = make_float2(W[(2 * k2) * HID + col], W[(2 * k2 + 1) * HID + col]);
    }

    int tile0 = blockIdx.x * 64;
    const float4* X4 = (const float4*)X;
#pragma unroll
    for (int i = tid; i < 64 * 16; i += 256) {
        int r = i >> 4, q = i & 15;
        int row = tile0 + r;
        xs[r][q] = (row < n) ? X4[(size_t)row * 16 + q]
                             : make_float4(0.f, 0.f, 0.f, 0.f);
    }
    __syncthreads();

    int warp = tid >> 5, lane = tid & 31;
    int r0 = warp * 8;

    float2 accA[8], accB[8];
#pragma unroll
    for (int r = 0; r < 8; r++) {
        accA[r] = make_float2(0.f, 0.f);
        accB[r] = make_float2(0.f, 0.f);
    }

#pragma unroll
    for (int q = 0; q < 16; q++) {
        float2 wA0 = Wp[(2 * q) * HID + lane];
        float2 wB0 = Wp[(2 * q) * HID + lane + 32];
        float2 wA1 = Wp[(2 * q + 1) * HID + lane];
        float2 wB1 = Wp[(2 * q + 1) * HID + lane + 32];
#pragma unroll
        for (int r = 0; r < 8; r++) {
            float4 xv = xs[r0 + r][q];
            float2 x0 = make_float2(xv.x, xv.y);
            float2 x1 = make_float2(xv.z, xv.w);
            fma2(accA[r], x0, wA0);
            fma2(accB[r], x0, wB0);
            fma2(accA[r], x1, wA1);
            fma2(accB[r], x1, wB1);
        }
    }

#pragma unroll
    for (int r = 0; r < 8; r++) {
        int row = tile0 + r0 + r;
        if (row < n) {
            out[(size_t)row * HID + lane]      = accA[r].x + accA[r].y;
            out[(size_t)row * HID + lane + 32] = accB[r].x + accB[r].y;
        }
    }
}

// ---------------------------------------------------------------------------
// One warp per node:
//   acc = h[v]*dinv[v] + sum_j h[csrc[j]]*dinv[csrc[j]]
//   out[v] = relu(dinv[v]*acc + b)
__global__ void gather_kernel(const float* __restrict__ b,
                              float2* __restrict__ out, int n) {
    int w = (blockIdx.x * blockDim.x + threadIdx.x) >> 5;
    int lane = threadIdx.x & 31;
    if (w >= n) return;
    int v = w;
    int beg = g_rowstart[v];
    int end = g_rowstart[v + 1];
    const float2* hs2 = (const float2*)g_hs;

    float dv = g_dinv[v];
    float2 self = hs2[(size_t)v * 32 + lane];
    float2 acc = make_float2(self.x * dv, self.y * dv);

    int j = beg;
    for (; j + 4 <= end; j += 4) {
        int s0 = g_csrc[j], s1 = g_csrc[j + 1];
        int s2 = g_csrc[j + 2], s3 = g_csrc[j + 3];
        float d0 = g_dinv[s0], d1 = g_dinv[s1];
        float d2 = g_dinv[s2], d3 = g_dinv[s3];
        float2 a0 = hs2[(size_t)s0 * 32 + lane];
        float2 a1 = hs2[(size_t)s1 * 32 + lane];
        float2 a2 = hs2[(size_t)s2 * 32 + lane];
        float2 a3 = hs2[(size_t)s3 * 32 + lane];
        acc.x = fmaf(a0.x, d0, acc.x); acc.y = fmaf(a0.y, d0, acc.y);
        acc.x = fmaf(a1.x, d1, acc.x); acc.y = fmaf(a1.y, d1, acc.y);
        acc.x = fmaf(a2.x, d2, acc.x); acc.y = fmaf(a2.y, d2, acc.y);
        acc.x = fmaf(a3.x, d3, acc.x); acc.y = fmaf(a3.y, d3, acc.y);
    }
    for (; j < end; j++) {
        int s = g_csrc[j];
        float ds = g_dinv[s];
        float2 a = hs2[(size_t)s * 32 + lane];
        acc.x = fmaf(a.x, ds, acc.x);
        acc.y = fmaf(a.y, ds, acc.y);
    }
    float2 bb = ((const float2*)b)[lane];
    float2 r;
    r.x = fmaxf(fmaf(dv, acc.x, bb.x), 0.f);
    r.y = fmaxf(fmaf(dv, acc.y, bb.y), 0.f);
    out[(size_t)v * 32 + lane] = r;
}

// ---------------------------------------------------------------------------
extern "C" void kernel_launch(void* const* d_in, const int* in_sizes, int n_in,
                              void* d_out, int out_size) {
    const float* x  = (const float*)d_in[0];
    const int*   ei = (const int*)d_in[1];
    const float* W1 = (const float*)d_in[2];
    const float* b1 = (const float*)d_in[3];
    const float* W2 = (const float*)d_in[4];
    const float* b2 = (const float*)d_in[5];

    int n = in_sizes[0] / HID;       // 100000
    int E = in_sizes[1] / 2;         // 1600000
    const int* src = ei;
    const int* dst = ei + E;

    float* hs  = nullptr; cudaGetSymbolAddress((void**)&hs,  g_hs);
    float* h1  = nullptr; cudaGetSymbolAddress((void**)&h1,  g_h1);
    int*   deg = nullptr; cudaGetSymbolAddress((void**)&deg, g_deg);

    // one-time stream/event creation (no device memory involved)
    static cudaStream_t s2 = nullptr;
    static cudaEvent_t evFork = nullptr, evJoin = nullptr;
    if (s2 == nullptr) {
        cudaStreamCreateWithFlags(&s2, cudaStreamNonBlocking);
        cudaEventCreateWithFlags(&evFork, cudaEventDisableTiming);
        cudaEventCreateWithFlags(&evJoin, cudaEventDisableTiming);
    }

    int nb_scan = (n + SCAN_B - 1) / SCAN_B;             // 196 (<=256)
    int gemm_blocks = (n + 63) / 64;                     // 1563
    int gather_blocks = (n * 32 + 255) / 256;            // 12500

    // ---- fork: layer-1 GEMM on side stream, CSR build on main stream ----
    cudaEventRecord(evFork, 0);
    cudaStreamWaitEvent(s2, evFork, 0);
    gemm_kernel<<<gemm_blocks, 256, 0, s2>>>(x, W1, hs, n);
    cudaEventRecord(evJoin, s2);

    cudaMemsetAsync(deg, 0, n * sizeof(int), 0);
    deg_count_kernel<<<(E + 255) / 256, 256>>>(dst, E);
    scan1_kernel<<<nb_scan, SCAN_B>>>(n);
    scan23_kernel<<<(n + 255) / 256, 256>>>(n, E, nb_scan);
    fill_kernel<<<(E + 255) / 256, 256>>>(src, dst, E);

    // ---- join, then gather1 / gemm2 / gather2 ----
    cudaStreamWaitEvent(0, evJoin, 0);
    gather_kernel<<<gather_blocks, 256>>>(b1, (float2*)h1, n);
    gemm_kernel<<<gemm_blocks, 256>>>(h1, W2, hs, n);
    gather_kernel<<<gather_blocks, 256>>>(b2, (float2*)d_out, n);
}